// round 3
// baseline (speedup 1.0000x reference)
#include <cuda_runtime.h>
#include <math_constants.h>

// LSS view transformer, GB300 sm_103a — gather formulation (no atomics).
//
// Static geometry: ix = trunc(((w*d̂)/3567*100 - 50 + 50)/0.8), iy analog with
// 1271; both monotone in d and in w/h. For each depth bin d, pixels feeding
// voxel (iy,ix) form a rectangle [hlo,hhi)x[wlo,whi) -> per-d inversion tables.
//
// k0: build inversion tables (deterministic, rebuilt every launch)
// k1: softmax over depth + lift: T[d][p][c] = sum_cam prob*feat  (coalesced)
// k2: per voxel, sum T over (d, rect) -> out (coalesced reads, smem-transposed
//     coalesced writes). No atomics anywhere; bitwise deterministic.

#define D_N   40
#define H_N   32
#define W_N   88
#define CAM_N 6
#define C_N   128
#define BEV   125
#define NPIX  (H_N * W_N)     // 2816
#define NVOX  (BEV * BEV)     // 15625
#define VG    16              // voxels per splat block

__device__ float g_T[(size_t)D_N * NPIX * C_N];   // (d, pixel, c) ~57.7MB
__device__ int g_wlo[D_N * BEV];
__device__ int g_whi[D_N * BEV];
__device__ int g_hlo[D_N * BEV];
__device__ int g_hhi[D_N * BEV];

// Exact fp32 op sequence of the reference (unfused; no FMA contraction).
__device__ __forceinline__ int ix_of(int w, float dv) {
    float xd = __fmul_rn((float)w, dv);
    float gx = __fadd_rn(__fmul_rn(__fdiv_rn(xd, 3567.0f), 100.0f), -50.0f);
    return (int)__fdiv_rn(__fadd_rn(gx, 50.0f), 0.8f);
}
__device__ __forceinline__ int iy_of(int h, float dv) {
    float yd = __fmul_rn((float)h, dv);
    float gy = __fadd_rn(__fmul_rn(__fdiv_rn(yd, 1271.0f), 100.0f), -50.0f);
    return (int)__fdiv_rn(__fadd_rn(gy, 50.0f), 0.8f);
}

// ---- k0: per-d inversion tables --------------------------------------------
__global__ void build_tables_kernel() {
    const int d = blockIdx.x;
    const int t = threadIdx.x;
    for (int i = t; i < BEV; i += blockDim.x) {
        g_wlo[d * BEV + i] = 0; g_whi[d * BEV + i] = 0;
        g_hlo[d * BEV + i] = 0; g_hhi[d * BEV + i] = 0;
    }
    __syncthreads();
    const float dv = (float)(d + 2);
    if (t == 0) {                       // invert ix(w,d): monotone in w
        int prev = -1;
        for (int w = 0; w < W_N; ++w) {
            int ix = ix_of(w, dv);
            if (ix >= BEV) break;       // monotone: rest also out of range
            if (ix != prev) { g_wlo[d * BEV + ix] = w; prev = ix; }
            g_whi[d * BEV + ix] = w + 1;
        }
    } else if (t == 32) {               // invert iy(h,d): monotone in h
        int prev = -1;
        for (int h = 0; h < H_N; ++h) {
            int iy = iy_of(h, dv);
            if (iy >= BEV) break;
            if (iy != prev) { g_hlo[d * BEV + iy] = h; prev = iy; }
            g_hhi[d * BEV + iy] = h + 1;
        }
    }
}

// ---- k1: softmax + lift ----------------------------------------------------
__global__ __launch_bounds__(256, 8) void lift_kernel(
    const float* __restrict__ img_feat,
    const float* __restrict__ depth_logits)
{
    __shared__ float s_p[CAM_N][D_N];
    __shared__ float s_mx[CAM_N], s_inv[CAM_N];
    __shared__ int   s_dmax;

    const int p   = blockIdx.x;
    const int h   = p / W_N;
    const int w   = p - h * W_N;
    const int tid = threadIdx.x;
    const int cam = tid / D_N;
    const int d   = tid - cam * D_N;

    if (tid < CAM_N * D_N)
        s_p[cam][d] = depth_logits[((cam * D_N + d) * H_N + h) * W_N + w];
    __syncthreads();

    if (tid < CAM_N) {
        float m = -CUDART_INF_F;
        #pragma unroll
        for (int i = 0; i < D_N; ++i) m = fmaxf(m, s_p[tid][i]);
        s_mx[tid] = m;
    }
    __syncthreads();
    if (tid < CAM_N * D_N)
        s_p[cam][d] = __expf(s_p[cam][d] - s_mx[cam]);
    __syncthreads();
    if (tid < CAM_N) {
        float s = 0.0f;
        #pragma unroll
        for (int i = 0; i < D_N; ++i) s += s_p[tid][i];
        s_inv[tid] = 1.0f / s;
    }
    if (tid == CAM_N) {                 // validity is a prefix in d
        int dm = D_N;
        for (int i = 0; i < D_N; ++i) {
            float dv = (float)(i + 2);
            if (ix_of(w, dv) >= BEV || iy_of(h, dv) >= BEV) { dm = i; break; }
        }
        s_dmax = dm;
    }
    __syncthreads();
    if (tid < CAM_N * D_N)
        s_p[cam][d] *= s_inv[cam];
    __syncthreads();

    const int c    = tid & (C_N - 1);
    const int half = tid >> 7;
    const int fb   = (c * H_N + h) * W_N + w;
    const int FS   = C_N * H_N * W_N;
    const float f0 = img_feat[fb + 0 * FS];
    const float f1 = img_feat[fb + 1 * FS];
    const float f2 = img_feat[fb + 2 * FS];
    const float f3 = img_feat[fb + 3 * FS];
    const float f4 = img_feat[fb + 4 * FS];
    const float f5 = img_feat[fb + 5 * FS];

    const int dmax = s_dmax;
    for (int dd = half; dd < dmax; dd += 2) {
        float val = s_p[0][dd] * f0 + s_p[1][dd] * f1 + s_p[2][dd] * f2
                  + s_p[3][dd] * f3 + s_p[4][dd] * f4 + s_p[5][dd] * f5;
        g_T[((size_t)dd * NPIX + p) * C_N + c] = val;
    }
}

// ---- k2: gather/splat ------------------------------------------------------
__global__ __launch_bounds__(128) void splat_kernel(float* __restrict__ out)
{
    const int iy  = blockIdx.y;
    const int ix0 = blockIdx.x * VG;
    const int c   = threadIdx.x;        // channel

    __shared__ float s_acc[VG][C_N];
    __shared__ int   s_h[D_N][2];

    if (c < 2 * D_N) {
        int d = c >> 1;
        if (c & 1) s_h[d][1] = g_hhi[d * BEV + iy];
        else       s_h[d][0] = g_hlo[d * BEV + iy];
    }
    __syncthreads();

    for (int v = 0; v < VG; ++v) {
        const int ix = ix0 + v;
        float acc = 0.0f;
        if (ix < BEV) {
            #pragma unroll 1
            for (int d = 0; d < D_N; ++d) {
                const int hlo = s_h[d][0], hhi = s_h[d][1];
                if (hlo >= hhi) continue;
                const int wlo = g_wlo[d * BEV + ix];
                const int whi = g_whi[d * BEV + ix];
                const float* base = g_T + (size_t)d * NPIX * C_N + c;
                for (int h = hlo; h < hhi; ++h) {
                    const float* row = base + (size_t)(h * W_N) * C_N;
                    for (int w = wlo; w < whi; ++w)
                        acc += row[(size_t)w * C_N];
                }
            }
        }
        s_acc[v][c] = acc;
    }
    __syncthreads();

    // transposed write: consecutive lanes -> consecutive ix (coalesced)
    for (int i = threadIdx.x; i < VG * C_N; i += 128) {
        const int cc = i >> 4;           // channel
        const int vv = i & (VG - 1);     // voxel within group
        const int ix = ix0 + vv;
        if (ix < BEV)
            out[(size_t)cc * NVOX + iy * BEV + ix] = s_acc[vv][cc];
    }
}

extern "C" void kernel_launch(void* const* d_in, const int* in_sizes, int n_in,
                              void* d_out, int out_size)
{
    const float* img_feat     = (const float*)d_in[0];
    const float* depth_logits = (const float*)d_in[1];
    float* out = (float*)d_out;

    build_tables_kernel<<<D_N, 64>>>();
    lift_kernel<<<NPIX, 256>>>(img_feat, depth_logits);
    splat_kernel<<<dim3((BEV + VG - 1) / VG, BEV), 128>>>(out);
}

// round 4
// speedup vs baseline: 5.8911x; 5.8911x over previous
#include <cuda_runtime.h>
#include <math_constants.h>

// LSS view transformer, GB300 sm_103a — scatter with vectorized reductions.
//
// Per-pixel block: softmax over depth (6 cams), static voxel index per depth
// (monotone in d -> contiguous equal-voxel runs), per-run per-cam prob sums,
// then ONE red.global.add.v4.f32 per (run, 4-channel group) into a
// voxel-major scratch (channels contiguous). Final kernel transposes the
// scratch into the channel-major output (covers every element, so no output
// memset needed).

#define D_N   40
#define H_N   32
#define W_N   88
#define CAM_N 6
#define C_N   128
#define BEV   125
#define NPIX  (H_N * W_N)
#define NVOX  (BEV * BEV)

__device__ float g_acc[(size_t)NVOX * C_N];   // (voxel, channel) ~8MB

__global__ __launch_bounds__(256, 8) void lss_scatter_kernel(
    const float* __restrict__ img_feat,
    const float* __restrict__ depth_logits)
{
    __shared__ float s_p[CAM_N][D_N];
    __shared__ float s_mx[CAM_N], s_inv[CAM_N];
    __shared__ int   s_run_vox[D_N];
    __shared__ int   s_run_lo[D_N + 1];
    __shared__ float s_wsum[D_N][CAM_N];
    __shared__ int   s_idx[D_N];
    __shared__ int   s_nr;

    const int p   = blockIdx.x;          // pixel id: h*88 + w
    const int h   = p / W_N;
    const int w   = p - h * W_N;
    const int tid = threadIdx.x;
    const int cam = tid / D_N;
    const int d   = tid - cam * D_N;

    if (tid < CAM_N * D_N)
        s_p[cam][d] = depth_logits[((cam * D_N + d) * H_N + h) * W_N + w];
    __syncthreads();

    if (tid < CAM_N) {
        float m = -CUDART_INF_F;
        #pragma unroll
        for (int i = 0; i < D_N; ++i) m = fmaxf(m, s_p[tid][i]);
        s_mx[tid] = m;
    }
    __syncthreads();
    if (tid < CAM_N * D_N)
        s_p[cam][d] = __expf(s_p[cam][d] - s_mx[cam]);
    __syncthreads();
    if (tid < CAM_N) {
        float s = 0.0f;
        #pragma unroll
        for (int i = 0; i < D_N; ++i) s += s_p[tid][i];
        s_inv[tid] = 1.0f / s;
    }
    __syncthreads();
    if (tid < CAM_N * D_N)
        s_p[cam][d] *= s_inv[cam];

    // ---- static voxel index per depth (exact reference fp32 op sequence,
    //      no FMA contraction) ----
    if (tid < D_N) {
        float dv = (float)(tid + 2);
        float xd = __fmul_rn((float)w, dv);
        float yd = __fmul_rn((float)h, dv);
        float gx = __fadd_rn(__fmul_rn(__fdiv_rn(xd, 3567.0f), 100.0f), -50.0f);
        float gy = __fadd_rn(__fmul_rn(__fdiv_rn(yd, 1271.0f), 100.0f), -50.0f);
        int ix = (int)__fdiv_rn(__fadd_rn(gx, 50.0f), 0.8f);
        int iy = (int)__fdiv_rn(__fadd_rn(gy, 50.0f), 0.8f);
        bool valid = (ix < BEV) && (iy < BEV);
        s_idx[tid] = valid ? (iy * BEV + ix) : -1;
    }
    __syncthreads();

    // ---- compact equal-voxel runs (validity is a prefix in d) ----
    if (tid == 0) {
        int nr = 0, prev = -2, end = D_N;
        for (int i = 0; i < D_N; ++i) {
            int v = s_idx[i];
            if (v < 0) { end = i; break; }
            if (v != prev) { s_run_vox[nr] = v; s_run_lo[nr] = i; ++nr; prev = v; }
        }
        s_run_lo[nr] = end;
        s_nr = nr;
    }
    __syncthreads();

    const int nr = s_nr;

    if (tid < nr * CAM_N) {
        int r = tid / CAM_N, cm = tid - r * CAM_N;
        float s = 0.0f;
        int lo = s_run_lo[r], hi = s_run_lo[r + 1];
        for (int i = lo; i < hi; ++i) s += s_p[cm][i];
        s_wsum[r][cm] = s;
    }
    __syncthreads();

    // ---- scatter: thread = (4-channel group, run slice) ----
    const int cg    = tid & 31;          // channel group: channels 4*cg..4*cg+3
    const int slice = tid >> 5;          // run slice 0..7
    const int c0    = cg << 2;
    const int FS    = C_N * H_N * W_N;

    float f[CAM_N][4];
    #pragma unroll
    for (int cm = 0; cm < CAM_N; ++cm)
        #pragma unroll
        for (int j = 0; j < 4; ++j)
            f[cm][j] = img_feat[cm * FS + ((c0 + j) * H_N + h) * W_N + w];

    for (int r = slice; r < nr; r += 8) {
        float v0 = 0.f, v1 = 0.f, v2 = 0.f, v3 = 0.f;
        #pragma unroll
        for (int cm = 0; cm < CAM_N; ++cm) {
            float ws = s_wsum[r][cm];
            v0 += ws * f[cm][0];
            v1 += ws * f[cm][1];
            v2 += ws * f[cm][2];
            v3 += ws * f[cm][3];
        }
        float* dst = g_acc + (size_t)s_run_vox[r] * C_N + c0;
        asm volatile("red.global.add.v4.f32 [%0], {%1,%2,%3,%4};"
                     :: "l"(dst), "f"(v0), "f"(v1), "f"(v2), "f"(v3)
                     : "memory");
    }
}

// ---- transpose scratch (voxel-major) -> out (channel-major) ----------------
__global__ __launch_bounds__(256) void transpose_kernel(float* __restrict__ out)
{
    __shared__ float s[32][C_N + 1];

    const int v0  = blockIdx.x * 32;
    const int tid = threadIdx.x;

    // coalesced read: consecutive threads -> consecutive channels
    #pragma unroll
    for (int i = 0; i < 16; ++i) {
        int vl = i * 2 + (tid >> 7);
        int c  = tid & (C_N - 1);
        int v  = v0 + vl;
        s[vl][c] = (v < NVOX) ? g_acc[(size_t)v * C_N + c] : 0.0f;
    }
    __syncthreads();

    // coalesced write: consecutive threads -> consecutive voxels
    const int vl = tid & 31;
    const int cb = tid >> 5;             // 8 channel slices
    const int v  = v0 + vl;
    if (v < NVOX) {
        for (int c = cb; c < C_N; c += 8)
            out[(size_t)c * NVOX + v] = s[vl][c];
    }
}

extern "C" void kernel_launch(void* const* d_in, const int* in_sizes, int n_in,
                              void* d_out, int out_size)
{
    const float* img_feat     = (const float*)d_in[0];
    const float* depth_logits = (const float*)d_in[1];
    float* out = (float*)d_out;

    void* acc_ptr = nullptr;
    cudaGetSymbolAddress(&acc_ptr, g_acc);
    cudaMemsetAsync(acc_ptr, 0, (size_t)NVOX * C_N * sizeof(float), 0);

    lss_scatter_kernel<<<NPIX, 256>>>(img_feat, depth_logits);
    transpose_kernel<<<(NVOX + 31) / 32, 256>>>(out);
}